// round 8
// baseline (speedup 1.0000x reference)
#include <cuda_runtime.h>
#include <cuda_bf16.h>
#include <cstdint>
#include <cstddef>

#define BATCH 4
#define TT    2048
#define CC    1024
#define NEG_INF (__int_as_float(0xff800000))

#define BM 128
#define BN 128
#define BK 32
#define NTH 256

// SMEM: 4 bf16 tiles of 128 rows x 40 (32 + 8 pad) per stage, 2 stages
#define ROWSTR 40
#define TILE_E (128 * ROWSTR)
#define OFF_AH 0
#define OFF_AL (1 * TILE_E)
#define OFF_BH (2 * TILE_E)
#define OFF_BL (3 * TILE_E)
#define STAGE_E (4 * TILE_E)               // 20480 elems = 40960 B
#define SMEM_BYTES (2 * STAGE_E * 2)       // 81920 B

typedef __nv_bfloat16 bf16;

// ---------------- scratch (device globals; allocation-free rule) ------------
__device__ bf16 g_qh[(size_t)BATCH*TT*CC],  g_ql[(size_t)BATCH*TT*CC];
__device__ bf16 g_kh[(size_t)BATCH*TT*CC],  g_kl[(size_t)BATCH*TT*CC];
__device__ bf16 g_vh[(size_t)BATCH*TT*CC],  g_vl[(size_t)BATCH*TT*CC];
__device__ bf16 g_Wqh[CC*CC], g_Wql[CC*CC];
__device__ bf16 g_Wkh[CC*CC], g_Wkl[CC*CC];
__device__ bf16 g_Wvh[CC*CC], g_Wvl[CC*CC];
__device__ bf16 g_Wfh[CC*CC], g_Wfl[CC*CC];
__device__ bf16 g_Qh[(size_t)BATCH*TT*CC],  g_Ql[(size_t)BATCH*TT*CC];
__device__ bf16 g_Kh[(size_t)BATCH*TT*CC],  g_Kl[(size_t)BATCH*TT*CC];
__device__ bf16 g_VTh[(size_t)BATCH*CC*TT], g_VTl[(size_t)BATCH*CC*TT];
__device__ bf16 g_Oh[(size_t)BATCH*TT*CC],  g_Ol[(size_t)BATCH*TT*CC];
__device__ bf16 g_Ph[(size_t)BATCH*TT*TT],  g_Pl[(size_t)BATCH*TT*TT];
__device__ float g_S[(size_t)BATCH*TT*TT];

// ---------------------------------------------------------------------------
__device__ __forceinline__ void mma_bf16(float* d, const uint32_t* a, uint32_t b0, uint32_t b1) {
    asm volatile(
        "mma.sync.aligned.m16n8k16.row.col.f32.bf16.bf16.f32 "
        "{%0,%1,%2,%3},{%4,%5,%6,%7},{%8,%9},{%0,%1,%2,%3};\n"
        : "+f"(d[0]), "+f"(d[1]), "+f"(d[2]), "+f"(d[3])
        : "r"(a[0]), "r"(a[1]), "r"(a[2]), "r"(a[3]), "r"(b0), "r"(b1));
}

#define CP16(dst_u32, src_ptr) \
    asm volatile("cp.async.cg.shared.global [%0], [%1], 16;" :: "r"(dst_u32), "l"(src_ptr))
#define CP_COMMIT() asm volatile("cp.async.commit_group;")
#define CP_WAIT1()  asm volatile("cp.async.wait_group 1;")

__device__ __forceinline__ void split1(float f, bf16& h, bf16& l) {
    h = __float2bfloat16_rn(f);
    l = __float2bfloat16_rn(f - __bfloat162float(h));
}

__device__ __forceinline__ void split_store4(const float* in, bf16* hi, bf16* lo, size_t i4) {
    float4 f = ((const float4*)in)[i4];
    bf16 h0,l0,h1,l1,h2,l2,h3,l3;
    split1(f.x,h0,l0); split1(f.y,h1,l1); split1(f.z,h2,l2); split1(f.w,h3,l3);
    ((__nv_bfloat162*)hi)[2*i4]   = __nv_bfloat162{h0,h1};
    ((__nv_bfloat162*)hi)[2*i4+1] = __nv_bfloat162{h2,h3};
    ((__nv_bfloat162*)lo)[2*i4]   = __nv_bfloat162{l0,l1};
    ((__nv_bfloat162*)lo)[2*i4+1] = __nv_bfloat162{l2,l3};
}

// batched split prepass: 3 equal-size tensors (q,k,v)
__global__ __launch_bounds__(256)
void split3(const float* __restrict__ a, const float* __restrict__ b, const float* __restrict__ c,
            bf16* __restrict__ ah, bf16* __restrict__ al,
            bf16* __restrict__ bh, bf16* __restrict__ bl,
            bf16* __restrict__ ch, bf16* __restrict__ cl, int n4)
{
    int i = blockIdx.x * 256 + threadIdx.x;
    if (i >= n4) return;
    const float* src[3] = {a, b, c};
    bf16* hi[3] = {ah, bh, ch};
    bf16* lo[3] = {al, bl, cl};
    const int s = blockIdx.y;
    split_store4(src[s], hi[s], lo[s], i);
}

// batched split prepass: 4 equal-size tensors (weights)
__global__ __launch_bounds__(256)
void split4(const float* __restrict__ a, const float* __restrict__ b,
            const float* __restrict__ c, const float* __restrict__ d,
            bf16* __restrict__ ah, bf16* __restrict__ al,
            bf16* __restrict__ bh, bf16* __restrict__ bl,
            bf16* __restrict__ ch, bf16* __restrict__ cl,
            bf16* __restrict__ dh, bf16* __restrict__ dl, int n4)
{
    int i = blockIdx.x * 256 + threadIdx.x;
    if (i >= n4) return;
    const float* src[4] = {a, b, c, d};
    bf16* hi[4] = {ah, bh, ch, dh};
    bf16* lo[4] = {al, bl, cl, dl};
    const int s = blockIdx.y;
    split_store4(src[s], hi[s], lo[s], i);
}

// ---------------------------------------------------------------------------
// Split-bf16 mma.sync GEMM-NT, pre-split operands, cp.async 2-stage pipeline.
//   C = alpha * A @ B^T (+bias) (+mask); 3-term: AhBh + AhBl + AlBh
// Cf!=null -> fp32 out; else Ch/Cl bf16 hi/lo (transC: transposed per batch)
// kvlim: K limited to (by+1)*128 (P@V causality)
// ---------------------------------------------------------------------------
__global__ __launch_bounds__(NTH, 2)
void gemm_mma(const bf16* __restrict__ Ah, const bf16* __restrict__ Al,
              const bf16* __restrict__ Bh, const bf16* __restrict__ Bl,
              const float* __restrict__ bias,
              float* __restrict__ Cf, bf16* __restrict__ Ch, bf16* __restrict__ Cl,
              int M, int N, int K,
              size_t sA, size_t sB, size_t sC,
              float alpha, int causal, int kvlim, int transC)
{
    const int bx = blockIdx.x, by = blockIdx.y, bz = blockIdx.z;
    if (causal && bx > by) return;

    const int m0 = by * BM, n0 = bx * BN;
    const int Keff = kvlim ? (by + 1) * BM : K;
    const int nch  = Keff / BK;

    extern __shared__ bf16 sm[];
    const uint32_t smb = (uint32_t)__cvta_generic_to_shared(sm);

    const int t = threadIdx.x, w = t >> 5, lane = t & 31;
    const int qr = lane >> 2, qc = (lane & 3) * 2;
    const int mb = (w & 1) * 64, nb = (w >> 1) * 32;

    // cp.async geometry: 2 16B-chunks per tile per thread
    const int r0 = (t * 2) >> 2,     c0 = (t * 2) & 3;
    const int r1 = r0,               c1 = c0 + 1;   // consecutive chunks share row

    // hoisted global base offsets (element units); advance by BK per chunk
    const bf16* pAh = Ah + (size_t)bz * sA + (size_t)(m0 + r0) * K + c0 * 8;
    const bf16* pAl = Al + (size_t)bz * sA + (size_t)(m0 + r0) * K + c0 * 8;
    const bf16* pBh = Bh + (size_t)bz * sB + (size_t)(n0 + r0) * K + c0 * 8;
    const bf16* pBl = Bl + (size_t)bz * sB + (size_t)(n0 + r0) * K + c0 * 8;
    const uint32_t dA0 = (uint32_t)((r0 * ROWSTR + c0 * 8) * 2);
    const uint32_t dA1 = (uint32_t)((r1 * ROWSTR + c1 * 8) * 2);

    float acc[4][4][4] = {};

    auto issue = [&](int i) {
        const int k0 = i * BK;
        const uint32_t stg = smb + (uint32_t)((i & 1) * STAGE_E * 2);
        CP16(stg + OFF_AH*2 + dA0, pAh + k0);
        CP16(stg + OFF_AH*2 + dA1, pAh + k0 + 8);
        CP16(stg + OFF_AL*2 + dA0, pAl + k0);
        CP16(stg + OFF_AL*2 + dA1, pAl + k0 + 8);
        CP16(stg + OFF_BH*2 + dA0, pBh + k0);
        CP16(stg + OFF_BH*2 + dA1, pBh + k0 + 8);
        CP16(stg + OFF_BL*2 + dA0, pBl + k0);
        CP16(stg + OFF_BL*2 + dA1, pBl + k0 + 8);
        CP_COMMIT();
    };

    issue(0);
    if (nch > 1) issue(1);

    for (int i = 0; i < nch; i++) {
        CP_WAIT1();
        __syncthreads();
        const bf16* stg = sm + (i & 1) * STAGE_E;
#pragma unroll
        for (int kk = 0; kk < BK; kk += 16) {
            uint32_t bhf[4][2], blf[4][2];
#pragma unroll
            for (int j = 0; j < 4; j++) {
                const int nr = nb + j * 8 + qr;
                bhf[j][0] = *(const uint32_t*)&stg[OFF_BH + nr * ROWSTR + kk + qc];
                bhf[j][1] = *(const uint32_t*)&stg[OFF_BH + nr * ROWSTR + kk + qc + 8];
                blf[j][0] = *(const uint32_t*)&stg[OFF_BL + nr * ROWSTR + kk + qc];
                blf[j][1] = *(const uint32_t*)&stg[OFF_BL + nr * ROWSTR + kk + qc + 8];
            }
#pragma unroll
            for (int ii = 0; ii < 4; ii++) {
                const int ar = mb + ii * 16 + qr;
                uint32_t ah[4], al[4];
                ah[0] = *(const uint32_t*)&stg[OFF_AH + ar * ROWSTR + kk + qc];
                ah[1] = *(const uint32_t*)&stg[OFF_AH + (ar + 8) * ROWSTR + kk + qc];
                ah[2] = *(const uint32_t*)&stg[OFF_AH + ar * ROWSTR + kk + qc + 8];
                ah[3] = *(const uint32_t*)&stg[OFF_AH + (ar + 8) * ROWSTR + kk + qc + 8];
                al[0] = *(const uint32_t*)&stg[OFF_AL + ar * ROWSTR + kk + qc];
                al[1] = *(const uint32_t*)&stg[OFF_AL + (ar + 8) * ROWSTR + kk + qc];
                al[2] = *(const uint32_t*)&stg[OFF_AL + ar * ROWSTR + kk + qc + 8];
                al[3] = *(const uint32_t*)&stg[OFF_AL + (ar + 8) * ROWSTR + kk + qc + 8];
#pragma unroll
                for (int j = 0; j < 4; j++) {
                    mma_bf16(acc[ii][j], ah, bhf[j][0], bhf[j][1]);
                    mma_bf16(acc[ii][j], ah, blf[j][0], blf[j][1]);
                    mma_bf16(acc[ii][j], al, bhf[j][0], bhf[j][1]);
                }
            }
        }
        __syncthreads();
        if (i + 2 < nch) issue(i + 2);
    }

    // ---- epilogue
    if (Cf) Cf += (size_t)bz * sC;
    if (Ch) { Ch += (size_t)bz * sC; Cl += (size_t)bz * sC; }
    const int diag = (causal && bx == by);
#pragma unroll
    for (int ii = 0; ii < 4; ii++) {
#pragma unroll
        for (int j = 0; j < 4; j++) {
            const int rA = m0 + mb + ii * 16 + qr;
            const int rB = rA + 8;
            const int cb = n0 + nb + j * 8 + qc;
            float v00 = acc[ii][j][0] * alpha, v01 = acc[ii][j][1] * alpha;
            float v10 = acc[ii][j][2] * alpha, v11 = acc[ii][j][3] * alpha;
            if (bias) {
                const float b0 = bias[cb], b1 = bias[cb + 1];
                v00 += b0; v01 += b1; v10 += b0; v11 += b1;
            }
            if (diag) {
                if (cb     > rA) v00 = NEG_INF;
                if (cb + 1 > rA) v01 = NEG_INF;
                if (cb     > rB) v10 = NEG_INF;
                if (cb + 1 > rB) v11 = NEG_INF;
            }
            if (Cf) {
                *(float2*)&Cf[(size_t)rA * N + cb] = make_float2(v00, v01);
                *(float2*)&Cf[(size_t)rB * N + cb] = make_float2(v10, v11);
            } else if (transC) {
                const size_t bo = (size_t)(rA >> 11) * ((size_t)CC * TT);
                const int mA = rA & (TT - 1), mB = rB & (TT - 1);
                bf16 h, l;
                split1(v00, h, l); Ch[bo + (size_t)cb*TT + mA] = h; Cl[bo + (size_t)cb*TT + mA] = l;
                split1(v01, h, l); Ch[bo + (size_t)(cb+1)*TT + mA] = h; Cl[bo + (size_t)(cb+1)*TT + mA] = l;
                split1(v10, h, l); Ch[bo + (size_t)cb*TT + mB] = h; Cl[bo + (size_t)cb*TT + mB] = l;
                split1(v11, h, l); Ch[bo + (size_t)(cb+1)*TT + mB] = h; Cl[bo + (size_t)(cb+1)*TT + mB] = l;
            } else {
                bf16 h0,l0,h1,l1;
                split1(v00,h0,l0); split1(v01,h1,l1);
                *(__nv_bfloat162*)&Ch[(size_t)rA*N + cb] = __nv_bfloat162{h0,h1};
                *(__nv_bfloat162*)&Cl[(size_t)rA*N + cb] = __nv_bfloat162{l0,l1};
                split1(v10,h0,l0); split1(v11,h1,l1);
                *(__nv_bfloat162*)&Ch[(size_t)rB*N + cb] = __nv_bfloat162{h0,h1};
                *(__nv_bfloat162*)&Cl[(size_t)rB*N + cb] = __nv_bfloat162{l0,l1};
            }
        }
    }
}

// ---------------------------------------------------------------------------
// Single-pass row softmax: S fp32 -> bf16 hi/lo probabilities.
// Row cached in registers (<=8 elems/thread). Valid len = ((row>>7)+1)*128.
// ---------------------------------------------------------------------------
__global__ __launch_bounds__(256)
void softmax_kernel(const float* __restrict__ S, bf16* __restrict__ Ph,
                    bf16* __restrict__ Pl)
{
    const int row = blockIdx.x;
    const int b   = blockIdx.y;
    const size_t base = ((size_t)b * TT + row) * TT;
    const float* Sr = S + base;
    const int ncols = ((row >> 7) + 1) << 7;
    const int t = threadIdx.x;
    const int lane = t & 31, wp = t >> 5;

    __shared__ float red[8];

    float vals[8];
    float mx = NEG_INF;
#pragma unroll
    for (int i = 0; i < 8; i++) {
        const int c = t + i * 256;
        vals[i] = (c < ncols) ? Sr[c] : NEG_INF;
        mx = fmaxf(mx, vals[i]);
    }
#pragma unroll
    for (int s = 16; s > 0; s >>= 1) mx = fmaxf(mx, __shfl_xor_sync(~0u, mx, s));
    if (lane == 0) red[wp] = mx;
    __syncthreads();
    mx = red[0];
#pragma unroll
    for (int i = 1; i < 8; i++) mx = fmaxf(mx, red[i]);

    float sum = 0.0f;
#pragma unroll
    for (int i = 0; i < 8; i++) {
        vals[i] = __expf(vals[i] - mx);   // exp(-inf)=0 for masked/invalid
        sum += vals[i];
    }
#pragma unroll
    for (int s = 16; s > 0; s >>= 1) sum += __shfl_xor_sync(~0u, sum, s);
    __syncthreads();
    if (lane == 0) red[wp] = sum;
    __syncthreads();
    sum = 0.0f;
#pragma unroll
    for (int i = 0; i < 8; i++) sum += red[i];
    const float inv = 1.0f / sum;

#pragma unroll
    for (int i = 0; i < 8; i++) {
        const int c = t + i * 256;
        if (c < ncols) {
            bf16 h, l;
            split1(vals[i] * inv, h, l);
            Ph[base + c] = h;
            Pl[base + c] = l;
        }
    }
}

// ---------------------------------------------------------------------------
extern "C" void kernel_launch(void* const* d_in, const int* in_sizes, int n_in,
                              void* d_out, int out_size)
{
    const float* q   = (const float*)d_in[0];
    const float* k   = (const float*)d_in[1];
    const float* v   = (const float*)d_in[2];
    const float* Wq  = (const float*)d_in[3];
    const float* bq  = (const float*)d_in[4];
    const float* Wk  = (const float*)d_in[5];
    const float* bk  = (const float*)d_in[6];
    const float* Wv  = (const float*)d_in[7];
    const float* bv  = (const float*)d_in[8];
    const float* Wff = (const float*)d_in[9];
    const float* bff = (const float*)d_in[10];
    float* out = (float*)d_out;

    bf16 *qh,*ql,*kh,*kl,*vh,*vl,*Wqh,*Wql,*Wkh,*Wkl,*Wvh,*Wvl,*Wfh,*Wfl;
    bf16 *Qh,*Ql,*Kh,*Kl,*VTh,*VTl,*Oh,*Ol,*Ph,*Pl;
    float* S;
    cudaGetSymbolAddress((void**)&qh, g_qh);   cudaGetSymbolAddress((void**)&ql, g_ql);
    cudaGetSymbolAddress((void**)&kh, g_kh);   cudaGetSymbolAddress((void**)&kl, g_kl);
    cudaGetSymbolAddress((void**)&vh, g_vh);   cudaGetSymbolAddress((void**)&vl, g_vl);
    cudaGetSymbolAddress((void**)&Wqh, g_Wqh); cudaGetSymbolAddress((void**)&Wql, g_Wql);
    cudaGetSymbolAddress((void**)&Wkh, g_Wkh); cudaGetSymbolAddress((void**)&Wkl, g_Wkl);
    cudaGetSymbolAddress((void**)&Wvh, g_Wvh); cudaGetSymbolAddress((void**)&Wvl, g_Wvl);
    cudaGetSymbolAddress((void**)&Wfh, g_Wfh); cudaGetSymbolAddress((void**)&Wfl, g_Wfl);
    cudaGetSymbolAddress((void**)&Qh, g_Qh);   cudaGetSymbolAddress((void**)&Ql, g_Ql);
    cudaGetSymbolAddress((void**)&Kh, g_Kh);   cudaGetSymbolAddress((void**)&Kl, g_Kl);
    cudaGetSymbolAddress((void**)&VTh, g_VTh); cudaGetSymbolAddress((void**)&VTl, g_VTl);
    cudaGetSymbolAddress((void**)&Oh, g_Oh);   cudaGetSymbolAddress((void**)&Ol, g_Ol);
    cudaGetSymbolAddress((void**)&Ph, g_Ph);   cudaGetSymbolAddress((void**)&Pl, g_Pl);
    cudaGetSymbolAddress((void**)&S,  g_S);

    cudaFuncSetAttribute(gemm_mma, cudaFuncAttributeMaxDynamicSharedMemorySize, SMEM_BYTES);

    const int M = BATCH * TT;          // 8192
    const int NQ4 = (M * CC) / 4;
    const int NW4 = (CC * CC) / 4;

    // 0) split raw inputs (2 launches)
    split3<<<dim3((NQ4 + 255)/256, 3), 256>>>(q, k, v, qh, ql, kh, kl, vh, vl, NQ4);
    split4<<<dim3((NW4 + 255)/256, 4), 256>>>(Wq, Wk, Wv, Wff,
                                              Wqh, Wql, Wkh, Wkl, Wvh, Wvl, Wfh, Wfl, NW4);

    const dim3 blk(NTH);

    // 1) Projections (outputs stay split; V transposed)
    gemm_mma<<<dim3(CC/BN, M/BM, 1), blk, SMEM_BYTES>>>(
        qh, ql, Wqh, Wql, bq, nullptr, Qh, Ql,
        M, CC, CC, 0, 0, 0, 1.0f, 0, 0, 0);
    gemm_mma<<<dim3(CC/BN, M/BM, 1), blk, SMEM_BYTES>>>(
        kh, kl, Wkh, Wkl, bk, nullptr, Kh, Kl,
        M, CC, CC, 0, 0, 0, 1.0f, 0, 0, 0);
    gemm_mma<<<dim3(CC/BN, M/BM, 1), blk, SMEM_BYTES>>>(
        vh, vl, Wvh, Wvl, bv, nullptr, VTh, VTl,
        M, CC, CC, 0, 0, 0, 1.0f, 0, 0, 1);

    // 2) Scores -> fp32 S (causal lower-tri blocks only)  [launch idx 5: profiled]
    gemm_mma<<<dim3(TT/BN, TT/BM, BATCH), blk, SMEM_BYTES>>>(
        Qh, Ql, Kh, Kl, nullptr, S, nullptr, nullptr,
        TT, TT, CC, (size_t)TT*CC, (size_t)TT*CC, (size_t)TT*TT,
        1.0f/32.0f, 1, 0, 0);

    // 3) softmax -> split probabilities
    softmax_kernel<<<dim3(TT, BATCH), dim3(256)>>>(S, Ph, Pl);

    // 4) O = P @ V (NT vs transposed V, causal K-limit) -> split O
    gemm_mma<<<dim3(CC/BN, TT/BM, BATCH), blk, SMEM_BYTES>>>(
        Ph, Pl, VTh, VTl, nullptr, nullptr, Oh, Ol,
        TT, CC, TT, (size_t)TT*TT, (size_t)CC*TT, (size_t)TT*CC,
        1.0f, 0, 1, 0);

    // 5) final projection -> fp32 out
    gemm_mma<<<dim3(CC/BN, M/BM, 1), blk, SMEM_BYTES>>>(
        Oh, Ol, Wfh, Wfl, bff, out, nullptr, nullptr,
        M, CC, CC, 0, 0, 0, 1.0f, 0, 0, 0);
}

// round 9
// speedup vs baseline: 1.0854x; 1.0854x over previous
#include <cuda_runtime.h>
#include <cuda_bf16.h>
#include <cstdint>
#include <cstddef>

#define BATCH 4
#define TT    2048
#define CC    1024
#define NEG_INF (__int_as_float(0xff800000))

#define BM 128
#define BN 128
#define BK 32
#define NTH 256

// SMEM: 4 bf16 tiles of 128 rows x 40 (32 + 8 pad) per stage, 2 stages
#define ROWSTR 40
#define TILE_E (128 * ROWSTR)
#define OFF_AH 0
#define OFF_AL (1 * TILE_E)
#define OFF_BH (2 * TILE_E)
#define OFF_BL (3 * TILE_E)
#define STAGE_E (4 * TILE_E)               // 20480 elems = 40960 B
#define SMEM_BYTES (2 * STAGE_E * 2)       // 81920 B

typedef __nv_bfloat16 bf16;

// ---------------- scratch (device globals; allocation-free rule) ------------
__device__ bf16 g_qh[(size_t)BATCH*TT*CC],  g_ql[(size_t)BATCH*TT*CC];
__device__ bf16 g_kh[(size_t)BATCH*TT*CC],  g_kl[(size_t)BATCH*TT*CC];
__device__ bf16 g_vh[(size_t)BATCH*TT*CC],  g_vl[(size_t)BATCH*TT*CC];
__device__ bf16 g_Wqh[CC*CC], g_Wql[CC*CC];
__device__ bf16 g_Wkh[CC*CC], g_Wkl[CC*CC];
__device__ bf16 g_Wvh[CC*CC], g_Wvl[CC*CC];
__device__ bf16 g_Wfh[CC*CC], g_Wfl[CC*CC];
__device__ bf16 g_Qh[(size_t)BATCH*TT*CC],  g_Ql[(size_t)BATCH*TT*CC];
__device__ bf16 g_Kh[(size_t)BATCH*TT*CC],  g_Kl[(size_t)BATCH*TT*CC];
__device__ bf16 g_VTh[(size_t)BATCH*CC*TT], g_VTl[(size_t)BATCH*CC*TT];
__device__ bf16 g_Oh[(size_t)BATCH*TT*CC],  g_Ol[(size_t)BATCH*TT*CC];
__device__ bf16 g_Ph[(size_t)BATCH*TT*TT],  g_Pl[(size_t)BATCH*TT*TT];
__device__ float g_S[(size_t)BATCH*TT*TT];

// ---------------------------------------------------------------------------
__device__ __forceinline__ void mma_bf16(float* d, const uint32_t* a, uint32_t b0, uint32_t b1) {
    asm volatile(
        "mma.sync.aligned.m16n8k16.row.col.f32.bf16.bf16.f32 "
        "{%0,%1,%2,%3},{%4,%5,%6,%7},{%8,%9},{%0,%1,%2,%3};\n"
        : "+f"(d[0]), "+f"(d[1]), "+f"(d[2]), "+f"(d[3])
        : "r"(a[0]), "r"(a[1]), "r"(a[2]), "r"(a[3]), "r"(b0), "r"(b1));
}

#define LDSM4(r, addr)                                                           \
    asm volatile("ldmatrix.sync.aligned.m8n8.x4.shared.b16 {%0,%1,%2,%3}, [%4];" \
        : "=r"((r)[0]), "=r"((r)[1]), "=r"((r)[2]), "=r"((r)[3]) : "r"(addr))

#define CP16(dst_u32, src_ptr) \
    asm volatile("cp.async.cg.shared.global [%0], [%1], 16;" :: "r"(dst_u32), "l"(src_ptr))
#define CP_COMMIT() asm volatile("cp.async.commit_group;")
#define CP_WAIT1()  asm volatile("cp.async.wait_group 1;")

__device__ __forceinline__ void split1(float f, bf16& h, bf16& l) {
    h = __float2bfloat16_rn(f);
    l = __float2bfloat16_rn(f - __bfloat162float(h));
}

__device__ __forceinline__ void split_store4(const float* in, bf16* hi, bf16* lo, size_t i4) {
    float4 f = ((const float4*)in)[i4];
    bf16 h0,l0,h1,l1,h2,l2,h3,l3;
    split1(f.x,h0,l0); split1(f.y,h1,l1); split1(f.z,h2,l2); split1(f.w,h3,l3);
    ((__nv_bfloat162*)hi)[2*i4]   = __nv_bfloat162{h0,h1};
    ((__nv_bfloat162*)hi)[2*i4+1] = __nv_bfloat162{h2,h3};
    ((__nv_bfloat162*)lo)[2*i4]   = __nv_bfloat162{l0,l1};
    ((__nv_bfloat162*)lo)[2*i4+1] = __nv_bfloat162{l2,l3};
}

// batched split prepass: 3 equal-size tensors (q,k,v)
__global__ __launch_bounds__(256)
void split3(const float* __restrict__ a, const float* __restrict__ b, const float* __restrict__ c,
            bf16* __restrict__ ah, bf16* __restrict__ al,
            bf16* __restrict__ bh, bf16* __restrict__ bl,
            bf16* __restrict__ ch, bf16* __restrict__ cl, int n4)
{
    int i = blockIdx.x * 256 + threadIdx.x;
    if (i >= n4) return;
    const float* src[3] = {a, b, c};
    bf16* hi[3] = {ah, bh, ch};
    bf16* lo[3] = {al, bl, cl};
    const int s = blockIdx.y;
    split_store4(src[s], hi[s], lo[s], i);
}

// batched split prepass: 4 equal-size tensors (weights)
__global__ __launch_bounds__(256)
void split4(const float* __restrict__ a, const float* __restrict__ b,
            const float* __restrict__ c, const float* __restrict__ d,
            bf16* __restrict__ ah, bf16* __restrict__ al,
            bf16* __restrict__ bh, bf16* __restrict__ bl,
            bf16* __restrict__ ch, bf16* __restrict__ cl,
            bf16* __restrict__ dh, bf16* __restrict__ dl, int n4)
{
    int i = blockIdx.x * 256 + threadIdx.x;
    if (i >= n4) return;
    const float* src[4] = {a, b, c, d};
    bf16* hi[4] = {ah, bh, ch, dh};
    bf16* lo[4] = {al, bl, cl, dl};
    const int s = blockIdx.y;
    split_store4(src[s], hi[s], lo[s], i);
}

// ---------------------------------------------------------------------------
// Split-bf16 mma.sync GEMM-NT, pre-split operands, cp.async 2-stage pipeline,
// ldmatrix fragment loads.
//   C = alpha * A @ B^T (+bias) (+mask); 3-term: AhBh + AhBl + AlBh
// Cf!=null -> fp32 out; else Ch/Cl bf16 hi/lo (transC: transposed per batch)
// kvlim: K limited to (by+1)*128 (P@V causality)
// ---------------------------------------------------------------------------
__global__ __launch_bounds__(NTH, 2)
void gemm_mma(const bf16* __restrict__ Ah, const bf16* __restrict__ Al,
              const bf16* __restrict__ Bh, const bf16* __restrict__ Bl,
              const float* __restrict__ bias,
              float* __restrict__ Cf, bf16* __restrict__ Ch, bf16* __restrict__ Cl,
              int M, int N, int K,
              size_t sA, size_t sB, size_t sC,
              float alpha, int causal, int kvlim, int transC)
{
    const int bx = blockIdx.x, by = blockIdx.y, bz = blockIdx.z;
    if (causal && bx > by) return;

    const int m0 = by * BM, n0 = bx * BN;
    const int Keff = kvlim ? (by + 1) * BM : K;
    const int nch  = Keff / BK;

    extern __shared__ bf16 sm[];
    const uint32_t smb = (uint32_t)__cvta_generic_to_shared(sm);

    const int t = threadIdx.x, w = t >> 5, lane = t & 31;
    const int qr = lane >> 2, qc = (lane & 3) * 2;
    const int mb = (w & 1) * 64, nb = (w >> 1) * 32;

    // cp.async geometry: 2 16B-chunks per tile per thread (same row, adjacent cols)
    const int r0 = (t * 2) >> 2, c0 = (t * 2) & 3;

    // hoisted global base offsets; advance by BK per chunk
    const bf16* pAh = Ah + (size_t)bz * sA + (size_t)(m0 + r0) * K + c0 * 8;
    const bf16* pAl = Al + (size_t)bz * sA + (size_t)(m0 + r0) * K + c0 * 8;
    const bf16* pBh = Bh + (size_t)bz * sB + (size_t)(n0 + r0) * K + c0 * 8;
    const bf16* pBl = Bl + (size_t)bz * sB + (size_t)(n0 + r0) * K + c0 * 8;
    const uint32_t dA0 = (uint32_t)((r0 * ROWSTR + c0 * 8) * 2);
    const uint32_t dA1 = dA0 + 16;

    // ldmatrix per-lane byte offsets (within a tile)
    //  A x4: groups (m0-7|k0)(m8-15|k0)(m0-7|k8)(m8-15|k8)
    uint32_t offA[4];
#pragma unroll
    for (int ii = 0; ii < 4; ii++)
        offA[ii] = (uint32_t)(((mb + ii * 16 + (lane & 15)) * ROWSTR + (lane >> 4) * 8) * 2);
    //  B x4 (pair jp covers n-tiles 2jp,2jp+1): groups (n0-7|k0)(n0-7|k8)(n8-15|k0)(n8-15|k8)
    uint32_t offB[2];
#pragma unroll
    for (int jp = 0; jp < 2; jp++)
        offB[jp] = (uint32_t)(((nb + jp * 16 + ((lane >> 4) * 8) + (lane & 7)) * ROWSTR
                               + ((lane >> 3) & 1) * 8) * 2);

    float acc[4][4][4] = {};

    auto issue = [&](int i) {
        const int k0 = i * BK;
        const uint32_t stg = smb + (uint32_t)((i & 1) * STAGE_E * 2);
        CP16(stg + OFF_AH*2 + dA0, pAh + k0);
        CP16(stg + OFF_AH*2 + dA1, pAh + k0 + 8);
        CP16(stg + OFF_AL*2 + dA0, pAl + k0);
        CP16(stg + OFF_AL*2 + dA1, pAl + k0 + 8);
        CP16(stg + OFF_BH*2 + dA0, pBh + k0);
        CP16(stg + OFF_BH*2 + dA1, pBh + k0 + 8);
        CP16(stg + OFF_BL*2 + dA0, pBl + k0);
        CP16(stg + OFF_BL*2 + dA1, pBl + k0 + 8);
        CP_COMMIT();
    };

    issue(0);
    if (nch > 1) issue(1);

    for (int i = 0; i < nch; i++) {
        CP_WAIT1();
        __syncthreads();
        const uint32_t stg = smb + (uint32_t)((i & 1) * STAGE_E * 2);
#pragma unroll
        for (int kk = 0; kk < BK; kk += 16) {
            const uint32_t kkb = (uint32_t)(kk * 2);
            uint32_t bh[2][4], bl[2][4];
#pragma unroll
            for (int jp = 0; jp < 2; jp++) {
                LDSM4(bh[jp], stg + OFF_BH*2 + offB[jp] + kkb);
                LDSM4(bl[jp], stg + OFF_BL*2 + offB[jp] + kkb);
            }
#pragma unroll
            for (int ii = 0; ii < 4; ii++) {
                uint32_t ah[4], al[4];
                LDSM4(ah, stg + OFF_AH*2 + offA[ii] + kkb);
                LDSM4(al, stg + OFF_AL*2 + offA[ii] + kkb);
#pragma unroll
                for (int j = 0; j < 4; j++) {
                    const uint32_t b0 = bh[j >> 1][(j & 1) * 2];
                    const uint32_t b1 = bh[j >> 1][(j & 1) * 2 + 1];
                    const uint32_t l0 = bl[j >> 1][(j & 1) * 2];
                    const uint32_t l1 = bl[j >> 1][(j & 1) * 2 + 1];
                    mma_bf16(acc[ii][j], ah, b0, b1);
                    mma_bf16(acc[ii][j], ah, l0, l1);
                    mma_bf16(acc[ii][j], al, b0, b1);
                }
            }
        }
        __syncthreads();
        if (i + 2 < nch) issue(i + 2);
    }

    // ---- epilogue
    if (Cf) Cf += (size_t)bz * sC;
    if (Ch) { Ch += (size_t)bz * sC; Cl += (size_t)bz * sC; }
    const int diag = (causal && bx == by);
#pragma unroll
    for (int ii = 0; ii < 4; ii++) {
#pragma unroll
        for (int j = 0; j < 4; j++) {
            const int rA = m0 + mb + ii * 16 + qr;
            const int rB = rA + 8;
            const int cb = n0 + nb + j * 8 + qc;
            float v00 = acc[ii][j][0] * alpha, v01 = acc[ii][j][1] * alpha;
            float v10 = acc[ii][j][2] * alpha, v11 = acc[ii][j][3] * alpha;
            if (bias) {
                const float b0 = bias[cb], b1 = bias[cb + 1];
                v00 += b0; v01 += b1; v10 += b0; v11 += b1;
            }
            if (diag) {
                if (cb     > rA) v00 = NEG_INF;
                if (cb + 1 > rA) v01 = NEG_INF;
                if (cb     > rB) v10 = NEG_INF;
                if (cb + 1 > rB) v11 = NEG_INF;
            }
            if (Cf) {
                *(float2*)&Cf[(size_t)rA * N + cb] = make_float2(v00, v01);
                *(float2*)&Cf[(size_t)rB * N + cb] = make_float2(v10, v11);
            } else if (transC) {
                const size_t bo = (size_t)(rA >> 11) * ((size_t)CC * TT);
                const int mA = rA & (TT - 1), mB = rB & (TT - 1);
                bf16 h, l;
                split1(v00, h, l); Ch[bo + (size_t)cb*TT + mA] = h; Cl[bo + (size_t)cb*TT + mA] = l;
                split1(v01, h, l); Ch[bo + (size_t)(cb+1)*TT + mA] = h; Cl[bo + (size_t)(cb+1)*TT + mA] = l;
                split1(v10, h, l); Ch[bo + (size_t)cb*TT + mB] = h; Cl[bo + (size_t)cb*TT + mB] = l;
                split1(v11, h, l); Ch[bo + (size_t)(cb+1)*TT + mB] = h; Cl[bo + (size_t)(cb+1)*TT + mB] = l;
            } else {
                bf16 h0,l0,h1,l1;
                split1(v00,h0,l0); split1(v01,h1,l1);
                *(__nv_bfloat162*)&Ch[(size_t)rA*N + cb] = __nv_bfloat162{h0,h1};
                *(__nv_bfloat162*)&Cl[(size_t)rA*N + cb] = __nv_bfloat162{l0,l1};
                split1(v10,h0,l0); split1(v11,h1,l1);
                *(__nv_bfloat162*)&Ch[(size_t)rB*N + cb] = __nv_bfloat162{h0,h1};
                *(__nv_bfloat162*)&Cl[(size_t)rB*N + cb] = __nv_bfloat162{l0,l1};
            }
        }
    }
}

// ---------------------------------------------------------------------------
// Single-pass row softmax: S fp32 -> bf16 hi/lo probabilities.
// Row cached in registers (<=8 elems/thread). Valid len = ((row>>7)+1)*128.
// ---------------------------------------------------------------------------
__global__ __launch_bounds__(256)
void softmax_kernel(const float* __restrict__ S, bf16* __restrict__ Ph,
                    bf16* __restrict__ Pl)
{
    const int row = blockIdx.x;
    const int b   = blockIdx.y;
    const size_t base = ((size_t)b * TT + row) * TT;
    const float* Sr = S + base;
    const int ncols = ((row >> 7) + 1) << 7;
    const int t = threadIdx.x;
    const int lane = t & 31, wp = t >> 5;

    __shared__ float red[8];

    float vals[8];
    float mx = NEG_INF;
#pragma unroll
    for (int i = 0; i < 8; i++) {
        const int c = t + i * 256;
        vals[i] = (c < ncols) ? Sr[c] : NEG_INF;
        mx = fmaxf(mx, vals[i]);
    }
#pragma unroll
    for (int s = 16; s > 0; s >>= 1) mx = fmaxf(mx, __shfl_xor_sync(~0u, mx, s));
    if (lane == 0) red[wp] = mx;
    __syncthreads();
    mx = red[0];
#pragma unroll
    for (int i = 1; i < 8; i++) mx = fmaxf(mx, red[i]);

    float sum = 0.0f;
#pragma unroll
    for (int i = 0; i < 8; i++) {
        vals[i] = __expf(vals[i] - mx);
        sum += vals[i];
    }
#pragma unroll
    for (int s = 16; s > 0; s >>= 1) sum += __shfl_xor_sync(~0u, sum, s);
    __syncthreads();
    if (lane == 0) red[wp] = sum;
    __syncthreads();
    sum = 0.0f;
#pragma unroll
    for (int i = 0; i < 8; i++) sum += red[i];
    const float inv = 1.0f / sum;

#pragma unroll
    for (int i = 0; i < 8; i++) {
        const int c = t + i * 256;
        if (c < ncols) {
            bf16 h, l;
            split1(vals[i] * inv, h, l);
            Ph[base + c] = h;
            Pl[base + c] = l;
        }
    }
}

// ---------------------------------------------------------------------------
extern "C" void kernel_launch(void* const* d_in, const int* in_sizes, int n_in,
                              void* d_out, int out_size)
{
    const float* q   = (const float*)d_in[0];
    const float* k   = (const float*)d_in[1];
    const float* v   = (const float*)d_in[2];
    const float* Wq  = (const float*)d_in[3];
    const float* bq  = (const float*)d_in[4];
    const float* Wk  = (const float*)d_in[5];
    const float* bk  = (const float*)d_in[6];
    const float* Wv  = (const float*)d_in[7];
    const float* bv  = (const float*)d_in[8];
    const float* Wff = (const float*)d_in[9];
    const float* bff = (const float*)d_in[10];
    float* out = (float*)d_out;

    bf16 *qh,*ql,*kh,*kl,*vh,*vl,*Wqh,*Wql,*Wkh,*Wkl,*Wvh,*Wvl,*Wfh,*Wfl;
    bf16 *Qh,*Ql,*Kh,*Kl,*VTh,*VTl,*Oh,*Ol,*Ph,*Pl;
    float* S;
    cudaGetSymbolAddress((void**)&qh, g_qh);   cudaGetSymbolAddress((void**)&ql, g_ql);
    cudaGetSymbolAddress((void**)&kh, g_kh);   cudaGetSymbolAddress((void**)&kl, g_kl);
    cudaGetSymbolAddress((void**)&vh, g_vh);   cudaGetSymbolAddress((void**)&vl, g_vl);
    cudaGetSymbolAddress((void**)&Wqh, g_Wqh); cudaGetSymbolAddress((void**)&Wql, g_Wql);
    cudaGetSymbolAddress((void**)&Wkh, g_Wkh); cudaGetSymbolAddress((void**)&Wkl, g_Wkl);
    cudaGetSymbolAddress((void**)&Wvh, g_Wvh); cudaGetSymbolAddress((void**)&Wvl, g_Wvl);
    cudaGetSymbolAddress((void**)&Wfh, g_Wfh); cudaGetSymbolAddress((void**)&Wfl, g_Wfl);
    cudaGetSymbolAddress((void**)&Qh, g_Qh);   cudaGetSymbolAddress((void**)&Ql, g_Ql);
    cudaGetSymbolAddress((void**)&Kh, g_Kh);   cudaGetSymbolAddress((void**)&Kl, g_Kl);
    cudaGetSymbolAddress((void**)&VTh, g_VTh); cudaGetSymbolAddress((void**)&VTl, g_VTl);
    cudaGetSymbolAddress((void**)&Oh, g_Oh);   cudaGetSymbolAddress((void**)&Ol, g_Ol);
    cudaGetSymbolAddress((void**)&Ph, g_Ph);   cudaGetSymbolAddress((void**)&Pl, g_Pl);
    cudaGetSymbolAddress((void**)&S,  g_S);

    cudaFuncSetAttribute(gemm_mma, cudaFuncAttributeMaxDynamicSharedMemorySize, SMEM_BYTES);

    const int M = BATCH * TT;          // 8192
    const int NQ4 = (M * CC) / 4;
    const int NW4 = (CC * CC) / 4;

    // 0) split raw inputs (2 launches)
    split3<<<dim3((NQ4 + 255)/256, 3), 256>>>(q, k, v, qh, ql, kh, kl, vh, vl, NQ4);
    split4<<<dim3((NW4 + 255)/256, 4), 256>>>(Wq, Wk, Wv, Wff,
                                              Wqh, Wql, Wkh, Wkl, Wvh, Wvl, Wfh, Wfl, NW4);

    const dim3 blk(NTH);

    // 1) Projections (outputs stay split; V transposed)
    gemm_mma<<<dim3(CC/BN, M/BM, 1), blk, SMEM_BYTES>>>(
        qh, ql, Wqh, Wql, bq, nullptr, Qh, Ql,
        M, CC, CC, 0, 0, 0, 1.0f, 0, 0, 0);
    gemm_mma<<<dim3(CC/BN, M/BM, 1), blk, SMEM_BYTES>>>(
        kh, kl, Wkh, Wkl, bk, nullptr, Kh, Kl,
        M, CC, CC, 0, 0, 0, 1.0f, 0, 0, 0);
    gemm_mma<<<dim3(CC/BN, M/BM, 1), blk, SMEM_BYTES>>>(
        vh, vl, Wvh, Wvl, bv, nullptr, VTh, VTl,
        M, CC, CC, 0, 0, 0, 1.0f, 0, 0, 1);

    // 2) Scores -> fp32 S (causal lower-tri blocks only)  [launch idx 5: profiled]
    gemm_mma<<<dim3(TT/BN, TT/BM, BATCH), blk, SMEM_BYTES>>>(
        Qh, Ql, Kh, Kl, nullptr, S, nullptr, nullptr,
        TT, TT, CC, (size_t)TT*CC, (size_t)TT*CC, (size_t)TT*TT,
        1.0f/32.0f, 1, 0, 0);

    // 3) softmax -> split probabilities
    softmax_kernel<<<dim3(TT, BATCH), dim3(256)>>>(S, Ph, Pl);

    // 4) O = P @ V (NT vs transposed V, causal K-limit) -> split O
    gemm_mma<<<dim3(CC/BN, TT/BM, BATCH), blk, SMEM_BYTES>>>(
        Ph, Pl, VTh, VTl, nullptr, nullptr, Oh, Ol,
        TT, CC, TT, (size_t)TT*TT, (size_t)CC*TT, (size_t)TT*CC,
        1.0f, 0, 1, 0);

    // 5) final projection -> fp32 out
    gemm_mma<<<dim3(CC/BN, M/BM, 1), blk, SMEM_BYTES>>>(
        Oh, Ol, Wfh, Wfl, bff, out, nullptr, nullptr,
        M, CC, CC, 0, 0, 0, 1.0f, 0, 0, 0);
}

// round 10
// speedup vs baseline: 1.1871x; 1.0937x over previous
#include <cuda_runtime.h>
#include <cuda_bf16.h>
#include <cstdint>
#include <cstddef>

#define BATCH 4
#define TT    2048
#define CC    1024
#define NEG_INF (__int_as_float(0xff800000))

#define BM 128
#define BN 128
#define BK 32
#define NTH 256

// SMEM: 4 bf16 tiles of 128 rows x 40 (32 + 8 pad) per stage, 2 stages
#define ROWSTR 40
#define TILE_E (128 * ROWSTR)
#define OFF_AH 0
#define OFF_AL (1 * TILE_E)
#define OFF_BH (2 * TILE_E)
#define OFF_BL (3 * TILE_E)
#define STAGE_E (4 * TILE_E)               // 20480 elems = 40960 B
#define SMEM_BYTES (2 * STAGE_E * 2)       // 81920 B

typedef __nv_bfloat16 bf16;

// ---------------- scratch (device globals; allocation-free rule) ------------
__device__ bf16 g_qh[(size_t)BATCH*TT*CC],  g_ql[(size_t)BATCH*TT*CC];
__device__ bf16 g_kh[(size_t)BATCH*TT*CC],  g_kl[(size_t)BATCH*TT*CC];
__device__ bf16 g_vh[(size_t)BATCH*TT*CC],  g_vl[(size_t)BATCH*TT*CC];
__device__ bf16 g_Wqh[CC*CC], g_Wql[CC*CC];
__device__ bf16 g_Wkh[CC*CC], g_Wkl[CC*CC];
__device__ bf16 g_Wvh[CC*CC], g_Wvl[CC*CC];
__device__ bf16 g_Wfh[CC*CC], g_Wfl[CC*CC];
__device__ bf16 g_Qh[(size_t)BATCH*TT*CC],  g_Ql[(size_t)BATCH*TT*CC];
__device__ bf16 g_Kh[(size_t)BATCH*TT*CC],  g_Kl[(size_t)BATCH*TT*CC];
__device__ bf16 g_VTh[(size_t)BATCH*CC*TT], g_VTl[(size_t)BATCH*CC*TT];
__device__ bf16 g_Oh[(size_t)BATCH*TT*CC],  g_Ol[(size_t)BATCH*TT*CC];
__device__ bf16 g_Ph[(size_t)BATCH*TT*TT],  g_Pl[(size_t)BATCH*TT*TT];
__device__ float g_S[(size_t)BATCH*TT*TT];

// ---------------------------------------------------------------------------
__device__ __forceinline__ void mma_bf16(float* d, const uint32_t* a, uint32_t b0, uint32_t b1) {
    asm volatile(
        "mma.sync.aligned.m16n8k16.row.col.f32.bf16.bf16.f32 "
        "{%0,%1,%2,%3},{%4,%5,%6,%7},{%8,%9},{%0,%1,%2,%3};\n"
        : "+f"(d[0]), "+f"(d[1]), "+f"(d[2]), "+f"(d[3])
        : "r"(a[0]), "r"(a[1]), "r"(a[2]), "r"(a[3]), "r"(b0), "r"(b1));
}

#define LDSM4(r, addr)                                                           \
    asm volatile("ldmatrix.sync.aligned.m8n8.x4.shared.b16 {%0,%1,%2,%3}, [%4];" \
        : "=r"((r)[0]), "=r"((r)[1]), "=r"((r)[2]), "=r"((r)[3]) : "r"(addr))

#define CP16(dst_u32, src_ptr) \
    asm volatile("cp.async.cg.shared.global [%0], [%1], 16;" :: "r"(dst_u32), "l"(src_ptr))
#define CP_COMMIT() asm volatile("cp.async.commit_group;")
#define CP_WAIT1()  asm volatile("cp.async.wait_group 1;")

__device__ __forceinline__ void split1(float f, bf16& h, bf16& l) {
    h = __float2bfloat16_rn(f);
    l = __float2bfloat16_rn(f - __bfloat162float(h));
}

// ---------------------------------------------------------------------------
// One fused split prepass for all 7 fp32 tensors -> bf16 hi/lo
// grid.y selects tensor; grid.x covers the largest tensor, small ones guard.
// ---------------------------------------------------------------------------
__global__ __launch_bounds__(256)
void split_all(const float* __restrict__ q, const float* __restrict__ k,
               const float* __restrict__ v, const float* __restrict__ Wq,
               const float* __restrict__ Wk, const float* __restrict__ Wv,
               const float* __restrict__ Wf,
               bf16* __restrict__ qh, bf16* __restrict__ ql,
               bf16* __restrict__ kh, bf16* __restrict__ kl,
               bf16* __restrict__ vh, bf16* __restrict__ vl,
               bf16* __restrict__ Wqh, bf16* __restrict__ Wql,
               bf16* __restrict__ Wkh, bf16* __restrict__ Wkl,
               bf16* __restrict__ Wvh, bf16* __restrict__ Wvl,
               bf16* __restrict__ Wfh, bf16* __restrict__ Wfl,
               int nbig4, int nsmall4)
{
    const int s = blockIdx.y;
    const int n4 = (s < 3) ? nbig4 : nsmall4;
    const int i = blockIdx.x * 256 + threadIdx.x;
    if (i >= n4) return;
    const float* src; bf16* hi; bf16* lo;
    switch (s) {
        case 0: src = q;  hi = qh;  lo = ql;  break;
        case 1: src = k;  hi = kh;  lo = kl;  break;
        case 2: src = v;  hi = vh;  lo = vl;  break;
        case 3: src = Wq; hi = Wqh; lo = Wql; break;
        case 4: src = Wk; hi = Wkh; lo = Wkl; break;
        case 5: src = Wv; hi = Wvh; lo = Wvl; break;
        default: src = Wf; hi = Wfh; lo = Wfl; break;
    }
    float4 f = ((const float4*)src)[i];
    bf16 h0,l0,h1,l1,h2,l2,h3,l3;
    split1(f.x,h0,l0); split1(f.y,h1,l1); split1(f.z,h2,l2); split1(f.w,h3,l3);
    ((__nv_bfloat162*)hi)[2*i]   = __nv_bfloat162{h0,h1};
    ((__nv_bfloat162*)hi)[2*i+1] = __nv_bfloat162{h2,h3};
    ((__nv_bfloat162*)lo)[2*i]   = __nv_bfloat162{l0,l1};
    ((__nv_bfloat162*)lo)[2*i+1] = __nv_bfloat162{l2,l3};
}

// ---------------------------------------------------------------------------
// Core split-bf16 mma.sync GEMM-NT tile: term-major MMA ordering.
// Computes C tile (m0,n0) of alpha*A@B^T(+bias)(+causal mask on diag).
// ---------------------------------------------------------------------------
__device__ __forceinline__ void gemm_core(
    const bf16* __restrict__ Ah, const bf16* __restrict__ Al,
    const bf16* __restrict__ Bh, const bf16* __restrict__ Bl,
    const float* __restrict__ bias,
    float* __restrict__ Cf, bf16* __restrict__ Ch, bf16* __restrict__ Cl,
    int N, int K, int m0, int n0, int Keff,
    float alpha, int diag, int transC)
{
    const int nch = Keff / BK;

    extern __shared__ bf16 sm[];
    const uint32_t smb = (uint32_t)__cvta_generic_to_shared(sm);

    const int t = threadIdx.x, w = t >> 5, lane = t & 31;
    const int qr = lane >> 2, qc = (lane & 3) * 2;
    const int mb = (w & 1) * 64, nb = (w >> 1) * 32;

    // cp.async geometry: 2 16B-chunks per tile per thread (same row, adjacent cols)
    const int r0 = (t * 2) >> 2, c0 = (t * 2) & 3;

    const bf16* pAh = Ah + (size_t)(m0 + r0) * K + c0 * 8;
    const bf16* pAl = Al + (size_t)(m0 + r0) * K + c0 * 8;
    const bf16* pBh = Bh + (size_t)(n0 + r0) * K + c0 * 8;
    const bf16* pBl = Bl + (size_t)(n0 + r0) * K + c0 * 8;
    const uint32_t dA0 = (uint32_t)((r0 * ROWSTR + c0 * 8) * 2);
    const uint32_t dA1 = dA0 + 16;

    // ldmatrix per-lane byte offsets
    uint32_t offA[4];
#pragma unroll
    for (int ii = 0; ii < 4; ii++)
        offA[ii] = (uint32_t)(((mb + ii * 16 + (lane & 15)) * ROWSTR + (lane >> 4) * 8) * 2);
    uint32_t offB[2];
#pragma unroll
    for (int jp = 0; jp < 2; jp++)
        offB[jp] = (uint32_t)(((nb + jp * 16 + ((lane >> 4) * 8) + (lane & 7)) * ROWSTR
                               + ((lane >> 3) & 1) * 8) * 2);

    float acc[4][4][4] = {};

    auto issue = [&](int i) {
        const int k0 = i * BK;
        const uint32_t stg = smb + (uint32_t)((i & 1) * STAGE_E * 2);
        CP16(stg + OFF_AH*2 + dA0, pAh + k0);
        CP16(stg + OFF_AH*2 + dA1, pAh + k0 + 8);
        CP16(stg + OFF_AL*2 + dA0, pAl + k0);
        CP16(stg + OFF_AL*2 + dA1, pAl + k0 + 8);
        CP16(stg + OFF_BH*2 + dA0, pBh + k0);
        CP16(stg + OFF_BH*2 + dA1, pBh + k0 + 8);
        CP16(stg + OFF_BL*2 + dA0, pBl + k0);
        CP16(stg + OFF_BL*2 + dA1, pBl + k0 + 8);
        CP_COMMIT();
    };

    issue(0);
    if (nch > 1) issue(1);

    for (int i = 0; i < nch; i++) {
        CP_WAIT1();
        __syncthreads();
        const uint32_t stg = smb + (uint32_t)((i & 1) * STAGE_E * 2);
#pragma unroll
        for (int kk = 0; kk < BK; kk += 16) {
            const uint32_t kkb = (uint32_t)(kk * 2);
            uint32_t bh[2][4], bl[2][4];
#pragma unroll
            for (int jp = 0; jp < 2; jp++) {
                LDSM4(bh[jp], stg + OFF_BH*2 + offB[jp] + kkb);
                LDSM4(bl[jp], stg + OFF_BL*2 + offB[jp] + kkb);
            }
#pragma unroll
            for (int ii = 0; ii < 4; ii++) {
                uint32_t ah[4], al[4];
                LDSM4(ah, stg + OFF_AH*2 + offA[ii] + kkb);
                LDSM4(al, stg + OFF_AL*2 + offA[ii] + kkb);
                // term-major: dependent MMAs on the same acc are 4 apart
#pragma unroll
                for (int j = 0; j < 4; j++)
                    mma_bf16(acc[ii][j], ah, bh[j >> 1][(j & 1)*2], bh[j >> 1][(j & 1)*2+1]);
#pragma unroll
                for (int j = 0; j < 4; j++)
                    mma_bf16(acc[ii][j], ah, bl[j >> 1][(j & 1)*2], bl[j >> 1][(j & 1)*2+1]);
#pragma unroll
                for (int j = 0; j < 4; j++)
                    mma_bf16(acc[ii][j], al, bh[j >> 1][(j & 1)*2], bh[j >> 1][(j & 1)*2+1]);
            }
        }
        __syncthreads();
        if (i + 2 < nch) issue(i + 2);
    }

    // ---- epilogue
#pragma unroll
    for (int ii = 0; ii < 4; ii++) {
#pragma unroll
        for (int j = 0; j < 4; j++) {
            const int rA = m0 + mb + ii * 16 + qr;
            const int rB = rA + 8;
            const int cb = n0 + nb + j * 8 + qc;
            float v00 = acc[ii][j][0] * alpha, v01 = acc[ii][j][1] * alpha;
            float v10 = acc[ii][j][2] * alpha, v11 = acc[ii][j][3] * alpha;
            if (bias) {
                const float b0 = bias[cb], b1 = bias[cb + 1];
                v00 += b0; v01 += b1; v10 += b0; v11 += b1;
            }
            if (diag) {
                if (cb     > rA) v00 = NEG_INF;
                if (cb + 1 > rA) v01 = NEG_INF;
                if (cb     > rB) v10 = NEG_INF;
                if (cb + 1 > rB) v11 = NEG_INF;
            }
            if (Cf) {
                *(float2*)&Cf[(size_t)rA * N + cb] = make_float2(v00, v01);
                *(float2*)&Cf[(size_t)rB * N + cb] = make_float2(v10, v11);
            } else if (transC) {
                const size_t bo = (size_t)(rA >> 11) * ((size_t)CC * TT);
                const int mA = rA & (TT - 1), mB = rB & (TT - 1);
                bf16 h, l;
                split1(v00, h, l); Ch[bo + (size_t)cb*TT + mA] = h; Cl[bo + (size_t)cb*TT + mA] = l;
                split1(v01, h, l); Ch[bo + (size_t)(cb+1)*TT + mA] = h; Cl[bo + (size_t)(cb+1)*TT + mA] = l;
                split1(v10, h, l); Ch[bo + (size_t)cb*TT + mB] = h; Cl[bo + (size_t)cb*TT + mB] = l;
                split1(v11, h, l); Ch[bo + (size_t)(cb+1)*TT + mB] = h; Cl[bo + (size_t)(cb+1)*TT + mB] = l;
            } else {
                bf16 h0,l0,h1,l1;
                split1(v00,h0,l0); split1(v01,h1,l1);
                *(__nv_bfloat162*)&Ch[(size_t)rA*N + cb] = __nv_bfloat162{h0,h1};
                *(__nv_bfloat162*)&Cl[(size_t)rA*N + cb] = __nv_bfloat162{l0,l1};
                split1(v10,h0,l0); split1(v11,h1,l1);
                *(__nv_bfloat162*)&Ch[(size_t)rB*N + cb] = __nv_bfloat162{h0,h1};
                *(__nv_bfloat162*)&Cl[(size_t)rB*N + cb] = __nv_bfloat162{l0,l1};
            }
        }
    }
}

// ---------------------------------------------------------------------------
// Fused Q/K/V projection: blockIdx.z in 0..2 selects the problem.
// M = BATCH*TT rows, N = K = CC. V output is transposed per batch.
// ---------------------------------------------------------------------------
__global__ __launch_bounds__(NTH, 2)
void gemm_qkv(const bf16* __restrict__ qh, const bf16* __restrict__ ql,
              const bf16* __restrict__ kh, const bf16* __restrict__ kl,
              const bf16* __restrict__ vh, const bf16* __restrict__ vl,
              const bf16* __restrict__ Wqh, const bf16* __restrict__ Wql,
              const bf16* __restrict__ Wkh, const bf16* __restrict__ Wkl,
              const bf16* __restrict__ Wvh, const bf16* __restrict__ Wvl,
              const float* __restrict__ bq, const float* __restrict__ bk,
              const float* __restrict__ bv,
              bf16* __restrict__ Qh, bf16* __restrict__ Ql,
              bf16* __restrict__ Kh, bf16* __restrict__ Kl,
              bf16* __restrict__ VTh, bf16* __restrict__ VTl)
{
    const int z = blockIdx.z;
    const bf16 *Ah, *Al, *Bh, *Bl;
    const float* bias;
    bf16 *Ch, *Cl;
    int transC = 0;
    if (z == 0)      { Ah=qh; Al=ql; Bh=Wqh; Bl=Wql; bias=bq; Ch=Qh;  Cl=Ql; }
    else if (z == 1) { Ah=kh; Al=kl; Bh=Wkh; Bl=Wkl; bias=bk; Ch=Kh;  Cl=Kl; }
    else             { Ah=vh; Al=vl; Bh=Wvh; Bl=Wvl; bias=bv; Ch=VTh; Cl=VTl; transC=1; }
    gemm_core(Ah, Al, Bh, Bl, bias, nullptr, Ch, Cl,
              CC, CC, blockIdx.y * BM, blockIdx.x * BN, CC,
              1.0f, 0, transC);
}

// ---------------------------------------------------------------------------
// General GEMM kernel (scores / P@V / final projection)
// ---------------------------------------------------------------------------
__global__ __launch_bounds__(NTH, 2)
void gemm_mma(const bf16* __restrict__ Ah, const bf16* __restrict__ Al,
              const bf16* __restrict__ Bh, const bf16* __restrict__ Bl,
              const float* __restrict__ bias,
              float* __restrict__ Cf, bf16* __restrict__ Ch, bf16* __restrict__ Cl,
              int N, int K,
              size_t sA, size_t sB, size_t sC,
              float alpha, int causal, int kvlim, int transC)
{
    const int bx = blockIdx.x, by = blockIdx.y, bz = blockIdx.z;
    if (causal && bx > by) return;
    const int Keff = kvlim ? (by + 1) * BM : K;
    gemm_core(Ah + (size_t)bz * sA, Al + (size_t)bz * sA,
              Bh + (size_t)bz * sB, Bl + (size_t)bz * sB, bias,
              Cf ? Cf + (size_t)bz * sC : nullptr,
              Ch ? Ch + (size_t)bz * sC : nullptr,
              Cl ? Cl + (size_t)bz * sC : nullptr,
              N, K, by * BM, bx * BN, Keff,
              alpha, causal && bx == by, transC);
}

// ---------------------------------------------------------------------------
// Single-pass row softmax: S fp32 -> bf16 hi/lo probabilities.
// ---------------------------------------------------------------------------
__global__ __launch_bounds__(256)
void softmax_kernel(const float* __restrict__ S, bf16* __restrict__ Ph,
                    bf16* __restrict__ Pl)
{
    const int row = blockIdx.x;
    const int b   = blockIdx.y;
    const size_t base = ((size_t)b * TT + row) * TT;
    const float* Sr = S + base;
    const int ncols = ((row >> 7) + 1) << 7;
    const int t = threadIdx.x;
    const int lane = t & 31, wp = t >> 5;

    __shared__ float red[8];

    float vals[8];
    float mx = NEG_INF;
#pragma unroll
    for (int i = 0; i < 8; i++) {
        const int c = t + i * 256;
        vals[i] = (c < ncols) ? Sr[c] : NEG_INF;
        mx = fmaxf(mx, vals[i]);
    }
#pragma unroll
    for (int s = 16; s > 0; s >>= 1) mx = fmaxf(mx, __shfl_xor_sync(~0u, mx, s));
    if (lane == 0) red[wp] = mx;
    __syncthreads();
    mx = red[0];
#pragma unroll
    for (int i = 1; i < 8; i++) mx = fmaxf(mx, red[i]);

    float sum = 0.0f;
#pragma unroll
    for (int i = 0; i < 8; i++) {
        vals[i] = __expf(vals[i] - mx);
        sum += vals[i];
    }
#pragma unroll
    for (int s = 16; s > 0; s >>= 1) sum += __shfl_xor_sync(~0u, sum, s);
    __syncthreads();
    if (lane == 0) red[wp] = sum;
    __syncthreads();
    sum = 0.0f;
#pragma unroll
    for (int i = 0; i < 8; i++) sum += red[i];
    const float inv = 1.0f / sum;

#pragma unroll
    for (int i = 0; i < 8; i++) {
        const int c = t + i * 256;
        if (c < ncols) {
            bf16 h, l;
            split1(vals[i] * inv, h, l);
            Ph[base + c] = h;
            Pl[base + c] = l;
        }
    }
}

// ---------------------------------------------------------------------------
extern "C" void kernel_launch(void* const* d_in, const int* in_sizes, int n_in,
                              void* d_out, int out_size)
{
    const float* q   = (const float*)d_in[0];
    const float* k   = (const float*)d_in[1];
    const float* v   = (const float*)d_in[2];
    const float* Wq  = (const float*)d_in[3];
    const float* bq  = (const float*)d_in[4];
    const float* Wk  = (const float*)d_in[5];
    const float* bk  = (const float*)d_in[6];
    const float* Wv  = (const float*)d_in[7];
    const float* bv  = (const float*)d_in[8];
    const float* Wff = (const float*)d_in[9];
    const float* bff = (const float*)d_in[10];
    float* out = (float*)d_out;

    bf16 *qh,*ql,*kh,*kl,*vh,*vl,*Wqh,*Wql,*Wkh,*Wkl,*Wvh,*Wvl,*Wfh,*Wfl;
    bf16 *Qh,*Ql,*Kh,*Kl,*VTh,*VTl,*Oh,*Ol,*Ph,*Pl;
    float* S;
    cudaGetSymbolAddress((void**)&qh, g_qh);   cudaGetSymbolAddress((void**)&ql, g_ql);
    cudaGetSymbolAddress((void**)&kh, g_kh);   cudaGetSymbolAddress((void**)&kl, g_kl);
    cudaGetSymbolAddress((void**)&vh, g_vh);   cudaGetSymbolAddress((void**)&vl, g_vl);
    cudaGetSymbolAddress((void**)&Wqh, g_Wqh); cudaGetSymbolAddress((void**)&Wql, g_Wql);
    cudaGetSymbolAddress((void**)&Wkh, g_Wkh); cudaGetSymbolAddress((void**)&Wkl, g_Wkl);
    cudaGetSymbolAddress((void**)&Wvh, g_Wvh); cudaGetSymbolAddress((void**)&Wvl, g_Wvl);
    cudaGetSymbolAddress((void**)&Wfh, g_Wfh); cudaGetSymbolAddress((void**)&Wfl, g_Wfl);
    cudaGetSymbolAddress((void**)&Qh, g_Qh);   cudaGetSymbolAddress((void**)&Ql, g_Ql);
    cudaGetSymbolAddress((void**)&Kh, g_Kh);   cudaGetSymbolAddress((void**)&Kl, g_Kl);
    cudaGetSymbolAddress((void**)&VTh, g_VTh); cudaGetSymbolAddress((void**)&VTl, g_VTl);
    cudaGetSymbolAddress((void**)&Oh, g_Oh);   cudaGetSymbolAddress((void**)&Ol, g_Ol);
    cudaGetSymbolAddress((void**)&Ph, g_Ph);   cudaGetSymbolAddress((void**)&Pl, g_Pl);
    cudaGetSymbolAddress((void**)&S,  g_S);

    cudaFuncSetAttribute(gemm_mma, cudaFuncAttributeMaxDynamicSharedMemorySize, SMEM_BYTES);
    cudaFuncSetAttribute(gemm_qkv, cudaFuncAttributeMaxDynamicSharedMemorySize, SMEM_BYTES);

    const int M = BATCH * TT;          // 8192
    const int NQ4 = (M * CC) / 4;      // 2M float4
    const int NW4 = (CC * CC) / 4;     // 256K float4

    // 0) one fused split prepass
    split_all<<<dim3((NQ4 + 255)/256, 7), 256>>>(
        q, k, v, Wq, Wk, Wv, Wff,
        qh, ql, kh, kl, vh, vl,
        Wqh, Wql, Wkh, Wkl, Wvh, Wvl, Wfh, Wfl, NQ4, NW4);

    const dim3 blk(NTH);

    // 1) fused Q/K/V projections (one launch, z selects problem)
    gemm_qkv<<<dim3(CC/BN, M/BM, 3), blk, SMEM_BYTES>>>(
        qh, ql, kh, kl, vh, vl,
        Wqh, Wql, Wkh, Wkl, Wvh, Wvl,
        bq, bk, bv, Qh, Ql, Kh, Kl, VTh, VTl);

    // 2) Scores -> fp32 S (causal lower-tri blocks only)
    gemm_mma<<<dim3(TT/BN, TT/BM, BATCH), blk, SMEM_BYTES>>>(
        Qh, Ql, Kh, Kl, nullptr, S, nullptr, nullptr,
        TT, CC, (size_t)TT*CC, (size_t)TT*CC, (size_t)TT*TT,
        1.0f/32.0f, 1, 0, 0);

    // 3) softmax -> split probabilities
    softmax_kernel<<<dim3(TT, BATCH), dim3(256)>>>(S, Ph, Pl);

    // 4) O = P @ V (NT vs transposed V, causal K-limit) -> split O
    gemm_mma<<<dim3(CC/BN, TT/BM, BATCH), blk, SMEM_BYTES>>>(
        Ph, Pl, VTh, VTl, nullptr, nullptr, Oh, Ol,
        CC, TT, (size_t)TT*TT, (size_t)CC*TT, (size_t)TT*CC,
        1.0f, 0, 1, 0);

    // 5) final projection -> fp32 out
    gemm_mma<<<dim3(CC/BN, M/BM, 1), blk, SMEM_BYTES>>>(
        Oh, Ol, Wfh, Wfl, bff, out, nullptr, nullptr,
        CC, CC, 0, 0, 0, 1.0f, 0, 0, 0);
}